// round 1
// baseline (speedup 1.0000x reference)
#include <cuda_runtime.h>
#include <mma.h>
#include <math.h>

using namespace nvcuda;

#define LN_EPS 1e-5f

// mid-residual scratch: x + attn_out, consumed by MLP kernel
__device__ float g_xres[4096 * 49 * 192];

typedef wmma::fragment<wmma::matrix_a, 16, 16, 8, wmma::precision::tf32, wmma::row_major> FragA;
typedef wmma::fragment<wmma::matrix_b, 16, 16, 8, wmma::precision::tf32, wmma::col_major> FragBc;
typedef wmma::fragment<wmma::matrix_b, 16, 16, 8, wmma::precision::tf32, wmma::row_major> FragBr;
typedef wmma::fragment<wmma::accumulator, 16, 16, 8, float> FragC;

template <typename F>
__device__ __forceinline__ void to_tf32(F& f) {
#pragma unroll
    for (int i = 0; i < f.num_elements; i++) f.x[i] = wmma::__float_to_tf32(f.x[i]);
}

// ---------------------------------------------------------------------------
// Kernel A: per-window  LN1 -> QKV -> attention -> proj -> +residual
// grid = 4096 windows, block = 256 (8 warps)
// smem: xn(64x192) q(64x32) k(64x32) v(64x32) S(64x64) o(64x192) = 139264 B
// ---------------------------------------------------------------------------
#define SMEM_A (64*192*4 + 3*64*32*4 + 64*64*4 + 64*192*4)

__global__ __launch_bounds__(256, 1) void attn_kernel(
    const float* __restrict__ x, const int* __restrict__ mask,
    const float* __restrict__ ln1g, const float* __restrict__ ln1b,
    const float* __restrict__ wqkv, const float* __restrict__ bqkv,
    const float* __restrict__ wproj, const float* __restrict__ bproj)
{
    extern __shared__ float sm[];
    float* xn = sm;                    // 64*192
    float* qs = xn + 64 * 192;         // 64*32
    float* ks = qs + 64 * 32;          // 64*32
    float* vs = ks + 64 * 32;          // 64*32
    float* S  = vs + 64 * 32;          // 64*64
    float* os = S + 64 * 64;           // 64*192

    const int tid = threadIdx.x;
    const int wid = tid >> 5;
    const int lane = tid & 31;
    const int win = blockIdx.x;
    const float* xw = x + win * 49 * 192;

    // load x (zero-pad rows 49..63)
    for (int idx = tid; idx < 64 * 192; idx += 256) {
        int r = idx / 192;
        int c = idx - r * 192;
        xn[idx] = (r < 49) ? xw[r * 192 + c] : 0.f;
    }
    __syncthreads();

    // LN1 in place (warp per row)
    for (int r = wid; r < 49; r += 8) {
        float v[6];
        float s = 0.f;
#pragma unroll
        for (int j = 0; j < 6; j++) { v[j] = xn[r * 192 + j * 32 + lane]; s += v[j]; }
#pragma unroll
        for (int o = 16; o; o >>= 1) s += __shfl_xor_sync(0xffffffffu, s, o);
        float mu = s * (1.f / 192.f);
        float va = 0.f;
#pragma unroll
        for (int j = 0; j < 6; j++) { float d = v[j] - mu; va += d * d; }
#pragma unroll
        for (int o = 16; o; o >>= 1) va += __shfl_xor_sync(0xffffffffu, va, o);
        float rstd = rsqrtf(va * (1.f / 192.f) + LN_EPS);
#pragma unroll
        for (int j = 0; j < 6; j++) {
            int c = j * 32 + lane;
            xn[r * 192 + c] = (v[j] - mu) * rstd * ln1g[c] + ln1b[c];
        }
    }
    __syncthreads();

    const float scale = 0.17677669529663687f;   // 1/sqrt(32)

    for (int h = 0; h < 6; h++) {
        // --- QKV for this head: 24 tiles (q/k/v x 4m x 2n), 3 per warp ---
#pragma unroll
        for (int it = 0; it < 3; it++) {
            int t = wid + it * 8;         // 0..23
            int matid = t >> 3;           // 0=q 1=k 2=v
            int r = t & 7;
            int mt = r & 3, nt = r >> 2;
            FragC c;
            wmma::fill_fragment(c, 0.f);
            for (int k0 = 0; k0 < 192; k0 += 8) {
                FragA a;
                wmma::load_matrix_sync(a, xn + mt * 16 * 192 + k0, 192);
                to_tf32(a);
                FragBc b;
                wmma::load_matrix_sync(b, wqkv + (matid * 192 + h * 32 + nt * 16) * 192 + k0, 192);
                to_tf32(b);
                wmma::mma_sync(c, a, b, c);
            }
            float* dst = (matid == 0 ? qs : (matid == 1 ? ks : vs)) + mt * 16 * 32 + nt * 16;
            wmma::store_matrix_sync(dst, c, 32, wmma::mem_row_major);
        }
        __syncthreads();

        // bias on rows < 49, zero padded rows
        for (int idx = tid; idx < 64 * 32; idx += 256) {
            int r = idx >> 5, cc = idx & 31;
            if (r < 49) {
                qs[idx] += bqkv[h * 32 + cc];
                ks[idx] += bqkv[192 + h * 32 + cc];
                vs[idx] += bqkv[384 + h * 32 + cc];
            } else {
                qs[idx] = 0.f; ks[idx] = 0.f; vs[idx] = 0.f;
            }
        }
        __syncthreads();

        // --- S = q k^T : 16 tiles (4x4), 2 per warp ---
#pragma unroll
        for (int it = 0; it < 2; it++) {
            int t = wid + it * 8;
            int mt = t >> 2, nt = t & 3;
            FragC c;
            wmma::fill_fragment(c, 0.f);
#pragma unroll
            for (int k0 = 0; k0 < 32; k0 += 8) {
                FragA a;
                wmma::load_matrix_sync(a, qs + mt * 16 * 32 + k0, 32);
                to_tf32(a);
                FragBc b;
                wmma::load_matrix_sync(b, ks + nt * 16 * 32 + k0, 32);
                to_tf32(b);
                wmma::mma_sync(c, a, b, c);
            }
            wmma::store_matrix_sync(S + mt * 16 * 64 + nt * 16, c, 64, wmma::mem_row_major);
        }
        __syncthreads();

        // --- masked softmax on rows < 49 (warp per row, 2 cols per lane) ---
        {
            const int* mrow_base = mask + win * 49 * 49;
            for (int r = wid; r < 49; r += 8) {
                const int* mrow = mrow_base + r * 49;
                int j1 = lane, j2 = lane + 32;
                float s1 = (mrow[j1] == 0) ? -3.0e38f : S[r * 64 + j1] * scale;
                float s2 = -3.0e38f;
                if (j2 < 49) s2 = (mrow[j2] == 0) ? -3.0e38f : S[r * 64 + j2] * scale;
                float m = fmaxf(s1, s2);
#pragma unroll
                for (int o = 16; o; o >>= 1) m = fmaxf(m, __shfl_xor_sync(0xffffffffu, m, o));
                float e1 = __expf(s1 - m);
                float e2 = (j2 < 49) ? __expf(s2 - m) : 0.f;
                float sum = e1 + e2;
#pragma unroll
                for (int o = 16; o; o >>= 1) sum += __shfl_xor_sync(0xffffffffu, sum, o);
                float inv = 1.f / sum;
                S[r * 64 + j1] = e1 * inv;
                S[r * 64 + j2] = e2 * inv;   // zero for padded / j2>=49 cols
            }
        }
        __syncthreads();

        // --- O = P @ V : 8 tiles (4m x 2n), 1 per warp ---
        {
            int mt = wid & 3, nt = wid >> 2;
            FragC c;
            wmma::fill_fragment(c, 0.f);
#pragma unroll
            for (int k0 = 0; k0 < 64; k0 += 8) {
                FragA a;
                wmma::load_matrix_sync(a, S + mt * 16 * 64 + k0, 64);
                to_tf32(a);
                FragBr b;
                wmma::load_matrix_sync(b, vs + k0 * 32 + nt * 16, 32);
                to_tf32(b);
                wmma::mma_sync(c, a, b, c);
            }
            wmma::store_matrix_sync(os + mt * 16 * 192 + h * 32 + nt * 16, c, 192, wmma::mem_row_major);
        }
        __syncthreads();
    }  // heads

    // --- proj: 48 tiles (4m x 12n), 6 per warp sharing A fragment ---
    {
        int mt = wid & 3;
        int nb = (wid >> 2) * 6;   // 0 or 6
        FragC acc[6];
#pragma unroll
        for (int i = 0; i < 6; i++) wmma::fill_fragment(acc[i], 0.f);
        for (int k0 = 0; k0 < 192; k0 += 8) {
            FragA a;
            wmma::load_matrix_sync(a, os + mt * 16 * 192 + k0, 192);
            to_tf32(a);
#pragma unroll
            for (int i = 0; i < 6; i++) {
                FragBc b;
                wmma::load_matrix_sync(b, wproj + (nb + i) * 16 * 192 + k0, 192);
                to_tf32(b);
                wmma::mma_sync(acc[i], a, b, acc[i]);
            }
        }
        // xn is free now: use as proj output buffer
#pragma unroll
        for (int i = 0; i < 6; i++)
            wmma::store_matrix_sync(xn + mt * 16 * 192 + (nb + i) * 16, acc[i], 192, wmma::mem_row_major);
    }
    __syncthreads();

    // epilogue: residual, write mid-state to scratch
    for (int idx = tid; idx < 49 * 192; idx += 256) {
        int c = idx % 192;
        g_xres[win * 49 * 192 + idx] = xw[idx] + xn[idx] + bproj[c];
    }
}

// ---------------------------------------------------------------------------
// Kernel B: 128-row tiles  LN2 -> FC1 -> GELU -> FC2 -> +residual -> out
// grid = 1568 (200704/128), block = 512 (16 warps)
// smem: xn(128x192) + h(128x192) = 196608 B
// ---------------------------------------------------------------------------
#define SMEM_B (128*192*4 * 2)

__global__ __launch_bounds__(512, 1) void mlp_kernel(
    const float* __restrict__ ln2g, const float* __restrict__ ln2b,
    const float* __restrict__ wfc1, const float* __restrict__ bfc1,
    const float* __restrict__ wfc2, const float* __restrict__ bfc2,
    float* __restrict__ out)
{
    extern __shared__ float sm[];
    float* xn = sm;                 // 128*192
    float* hs = sm + 128 * 192;     // 128*192 (hid chunk / out buffer)

    const int tid = threadIdx.x;
    const int wid = tid >> 5;
    const int lane = tid & 31;
    const int row0 = blockIdx.x * 128;
    const float* xr = g_xres + row0 * 192;

    // LN2 (warp per row; keep row in regs, one global read)
    for (int r = wid; r < 128; r += 16) {
        float v[6];
        float s = 0.f;
#pragma unroll
        for (int j = 0; j < 6; j++) { v[j] = xr[r * 192 + j * 32 + lane]; s += v[j]; }
#pragma unroll
        for (int o = 16; o; o >>= 1) s += __shfl_xor_sync(0xffffffffu, s, o);
        float mu = s * (1.f / 192.f);
        float va = 0.f;
#pragma unroll
        for (int j = 0; j < 6; j++) { float d = v[j] - mu; va += d * d; }
#pragma unroll
        for (int o = 16; o; o >>= 1) va += __shfl_xor_sync(0xffffffffu, va, o);
        float rstd = rsqrtf(va * (1.f / 192.f) + LN_EPS);
#pragma unroll
        for (int j = 0; j < 6; j++) {
            int c = j * 32 + lane;
            xn[r * 192 + c] = (v[j] - mu) * rstd * ln2g[c] + ln2b[c];
        }
    }
    __syncthreads();

    // out tile ownership: 8m x 12n tiles of 16x16; warp -> m = wid%8, n block of 6
    const int mt = wid & 7;
    const int nb = (wid >> 3) * 6;   // 0 or 6
    FragC acc[6];
#pragma unroll
    for (int i = 0; i < 6; i++) wmma::fill_fragment(acc[i], 0.f);

    for (int ch = 0; ch < 4; ch++) {
        const int hid0 = ch * 192;

        // FC1 chunk -> hs  (2 groups of 3 tiles to bound registers)
#pragma unroll
        for (int g = 0; g < 2; g++) {
            FragC f[3];
#pragma unroll
            for (int i = 0; i < 3; i++) wmma::fill_fragment(f[i], 0.f);
            for (int k0 = 0; k0 < 192; k0 += 8) {
                FragA a;
                wmma::load_matrix_sync(a, xn + mt * 16 * 192 + k0, 192);
                to_tf32(a);
#pragma unroll
                for (int i = 0; i < 3; i++) {
                    int n = nb + g * 3 + i;
                    FragBc b;
                    wmma::load_matrix_sync(b, wfc1 + (hid0 + n * 16) * 192 + k0, 192);
                    to_tf32(b);
                    wmma::mma_sync(f[i], a, b, f[i]);
                }
            }
#pragma unroll
            for (int i = 0; i < 3; i++)
                wmma::store_matrix_sync(hs + mt * 16 * 192 + (nb + g * 3 + i) * 16, f[i],
                                        192, wmma::mem_row_major);
        }
        __syncthreads();

        // bias + exact GELU in place
        for (int idx = tid; idx < 128 * 192; idx += 512) {
            int hh = idx % 192;
            float v = hs[idx] + bfc1[hid0 + hh];
            hs[idx] = 0.5f * v * (1.f + erff(v * 0.70710678118654752f));
        }
        __syncthreads();

        // FC2 partial accumulate (persistent acc)
        for (int k0 = 0; k0 < 192; k0 += 8) {
            FragA a;
            wmma::load_matrix_sync(a, hs + mt * 16 * 192 + k0, 192);
            to_tf32(a);
#pragma unroll
            for (int i = 0; i < 6; i++) {
                int n = nb + i;
                FragBc b;
                wmma::load_matrix_sync(b, wfc2 + (n * 16) * 768 + hid0 + k0, 768);
                to_tf32(b);
                wmma::mma_sync(acc[i], a, b, acc[i]);
            }
        }
        __syncthreads();   // before next chunk overwrites hs
    }

    // epilogue: acc -> hs, then residual + bias -> out
#pragma unroll
    for (int i = 0; i < 6; i++)
        wmma::store_matrix_sync(hs + mt * 16 * 192 + (nb + i) * 16, acc[i], 192, wmma::mem_row_major);
    __syncthreads();
    for (int idx = tid; idx < 128 * 192; idx += 512) {
        int c = idx % 192;
        out[row0 * 192 + idx] = xr[idx] + hs[idx] + bfc2[c];
    }
}

// ---------------------------------------------------------------------------

extern "C" void kernel_launch(void* const* d_in, const int* in_sizes, int n_in,
                              void* d_out, int out_size)
{
    const float* x     = (const float*)d_in[0];
    const int*   msk   = (const int*)  d_in[1];
    const float* ln1g  = (const float*)d_in[2];
    const float* ln1b  = (const float*)d_in[3];
    const float* wqkv  = (const float*)d_in[4];
    const float* bqkv  = (const float*)d_in[5];
    const float* wproj = (const float*)d_in[6];
    const float* bproj = (const float*)d_in[7];
    const float* ln2g  = (const float*)d_in[8];
    const float* ln2b  = (const float*)d_in[9];
    const float* wfc1  = (const float*)d_in[10];
    const float* bfc1  = (const float*)d_in[11];
    const float* wfc2  = (const float*)d_in[12];
    const float* bfc2  = (const float*)d_in[13];
    float* out = (float*)d_out;

    cudaFuncSetAttribute(attn_kernel, cudaFuncAttributeMaxDynamicSharedMemorySize, SMEM_A);
    cudaFuncSetAttribute(mlp_kernel,  cudaFuncAttributeMaxDynamicSharedMemorySize, SMEM_B);

    attn_kernel<<<4096, 256, SMEM_A>>>(x, msk, ln1g, ln1b, wqkv, bqkv, wproj, bproj);
    mlp_kernel<<<1568, 512, SMEM_B>>>(ln2g, ln2b, wfc1, bfc1, wfc2, bfc2, out);
}

// round 2
// speedup vs baseline: 2.8792x; 2.8792x over previous
#include <cuda_runtime.h>
#include <cuda_bf16.h>
#include <mma.h>
#include <math.h>

using namespace nvcuda;
typedef __nv_bfloat16 bf16;

#define LN_EPS 1e-5f

// persistent scratch (device globals: allocation-free)
__device__ float g_xres[4096 * 49 * 192];          // mid residual
__device__ bf16  g_hmid[(size_t)200704 * 768];     // GELU(fc1) activations
__device__ bf16  g_wqkv[576 * 192];
__device__ bf16  g_wproj[192 * 192];
__device__ bf16  g_wfc1[768 * 192];
__device__ bf16  g_wfc2[192 * 768];

typedef wmma::fragment<wmma::matrix_a, 16, 16, 16, bf16, wmma::row_major> FA;
typedef wmma::fragment<wmma::matrix_b, 16, 16, 16, bf16, wmma::col_major> FBc;
typedef wmma::fragment<wmma::matrix_b, 16, 16, 16, bf16, wmma::row_major> FBr;
typedef wmma::fragment<wmma::accumulator, 16, 16, 16, float> FC;

// ---------------------------------------------------------------------------
__global__ void cvt_all(const float* __restrict__ wqkv, const float* __restrict__ wproj,
                        const float* __restrict__ wfc1, const float* __restrict__ wfc2)
{
    int i = blockIdx.x * 256 + threadIdx.x;
    if (i < 110592) g_wqkv[i]  = __float2bfloat16(wqkv[i]);
    if (i < 36864)  g_wproj[i] = __float2bfloat16(wproj[i]);
    if (i < 147456) {
        g_wfc1[i] = __float2bfloat16(wfc1[i]);
        g_wfc2[i] = __float2bfloat16(wfc2[i]);
    }
}

// ---------------------------------------------------------------------------
// Kernel A: per-window  LN1 -> QKV -> attention -> proj -> +residual -> g_xres
// grid=4096, block=256 (8 warps), smem=93184 B -> 2 CTAs/SM
// ---------------------------------------------------------------------------
#define AT_SM 93184

__global__ __launch_bounds__(256, 2) void attn_kernel(
    const float* __restrict__ x, const int* __restrict__ mask,
    const float* __restrict__ ln1g, const float* __restrict__ ln1b,
    const float* __restrict__ bqkv, const float* __restrict__ bproj)
{
    extern __shared__ char smc[];
    bf16*  xn    = (bf16*)smc;                 // 64x200 bf16   25600
    bf16*  qs    = (bf16*)(smc + 25600);       // 64x40  bf16    5120
    bf16*  ks    = (bf16*)(smc + 30720);       // 64x40
    bf16*  vs    = (bf16*)(smc + 35840);       // 64x40
    float* S     = (float*)(smc + 40960);      // 64x68  f32    17408
    bf16*  P     = (bf16*)(smc + 58368);       // 64x72  bf16    9216
    bf16*  os    = (bf16*)(smc + 67584);       // 64x200 bf16   25600
    float* fbuf  = (float*)(smc + 40960);      // 64x100 f32 (aliases S+P)
    float* pvbuf = (float*)(smc + 40960);      // 64x40  f32 (aliases S)

    const int tid = threadIdx.x;
    const int wid = tid >> 5;
    const int lane = tid & 31;
    const int win = blockIdx.x;
    const float* xw = x + win * 49 * 192;

    // LN1 -> xn (bf16); zero padded rows 49..63
    for (int r = wid; r < 64; r += 8) {
        if (r < 49) {
            float v[6]; float s = 0.f;
#pragma unroll
            for (int j = 0; j < 6; j++) { v[j] = xw[r * 192 + j * 32 + lane]; s += v[j]; }
#pragma unroll
            for (int o = 16; o; o >>= 1) s += __shfl_xor_sync(0xffffffffu, s, o);
            float mu = s * (1.f / 192.f);
            float va = 0.f;
#pragma unroll
            for (int j = 0; j < 6; j++) { float d = v[j] - mu; va += d * d; }
#pragma unroll
            for (int o = 16; o; o >>= 1) va += __shfl_xor_sync(0xffffffffu, va, o);
            float rstd = rsqrtf(va * (1.f / 192.f) + LN_EPS);
#pragma unroll
            for (int j = 0; j < 6; j++) {
                int c = j * 32 + lane;
                xn[r * 200 + c] = __float2bfloat16((v[j] - mu) * rstd * ln1g[c] + ln1b[c]);
            }
        } else {
#pragma unroll
            for (int j = 0; j < 6; j++) xn[r * 200 + j * 32 + lane] = __float2bfloat16(0.f);
        }
    }
    __syncthreads();

    const float scale = 0.17677669529663687f;  // 1/sqrt(32)
    const int mtq = wid & 3, ngq = wid >> 2;

    for (int h = 0; h < 6; h++) {
        // --- QKV head slice: out 64x96 (q|k|v), warp = (mt, 3 n-tiles) ---
        {
            FC acc[3];
#pragma unroll
            for (int j = 0; j < 3; j++) wmma::fill_fragment(acc[j], 0.f);
            for (int k0 = 0; k0 < 192; k0 += 16) {
                FA a;
                wmma::load_matrix_sync(a, xn + mtq * 16 * 200 + k0, 200);
#pragma unroll
                for (int j = 0; j < 3; j++) {
                    int nt = ngq * 3 + j;
                    int n0 = (nt >> 1) * 192 + h * 32 + (nt & 1) * 16;
                    FBc b;
                    wmma::load_matrix_sync(b, g_wqkv + n0 * 192 + k0, 192);
                    wmma::mma_sync(acc[j], a, b, acc[j]);
                }
            }
#pragma unroll
            for (int j = 0; j < 3; j++)
                wmma::store_matrix_sync(fbuf + mtq * 16 * 100 + (ngq * 3 + j) * 16,
                                        acc[j], 100, wmma::mem_row_major);
        }
        __syncthreads();

        // convert fp32 -> bf16 (+bias, zero padded rows)
        for (int idx = tid; idx < 64 * 96; idx += 256) {
            int r = idx / 96, c = idx - r * 96;
            int matid = c >> 5, cc = c & 31;
            float v = (r < 49) ? fbuf[r * 100 + c] + bqkv[matid * 192 + h * 32 + cc] : 0.f;
            bf16* dst = (matid == 0) ? qs : ((matid == 1) ? ks : vs);
            dst[r * 40 + cc] = __float2bfloat16(v);
        }
        __syncthreads();

        // --- S = q k^T : 16 tiles, 2/warp ---
#pragma unroll
        for (int it = 0; it < 2; it++) {
            int t = wid + it * 8;
            int mt = t & 3, nt = t >> 2;
            FC c;
            wmma::fill_fragment(c, 0.f);
#pragma unroll
            for (int k0 = 0; k0 < 32; k0 += 16) {
                FA a;
                wmma::load_matrix_sync(a, qs + mt * 16 * 40 + k0, 40);
                FBc b;
                wmma::load_matrix_sync(b, ks + nt * 16 * 40 + k0, 40);
                wmma::mma_sync(c, a, b, c);
            }
            wmma::store_matrix_sync(S + mt * 16 * 68 + nt * 16, c, 68, wmma::mem_row_major);
        }
        __syncthreads();

        // --- masked softmax (fp32), write P bf16 ---
        {
            const int* mrow_base = mask + win * 49 * 49;
            for (int r = wid; r < 49; r += 8) {
                const int* mrow = mrow_base + r * 49;
                int j2 = lane + 32;
                float s1 = (mrow[lane] == 0) ? -1e30f : S[r * 68 + lane] * scale;
                float s2 = (j2 < 49 && mrow[j2] != 0) ? S[r * 68 + j2] * scale : -1e30f;
                float m = fmaxf(s1, s2);
#pragma unroll
                for (int o = 16; o; o >>= 1) m = fmaxf(m, __shfl_xor_sync(0xffffffffu, m, o));
                float e1 = __expf(s1 - m);
                float e2 = (j2 < 49) ? __expf(s2 - m) : 0.f;
                float sum = e1 + e2;
#pragma unroll
                for (int o = 16; o; o >>= 1) sum += __shfl_xor_sync(0xffffffffu, sum, o);
                float inv = 1.f / sum;
                P[r * 72 + lane] = __float2bfloat16(e1 * inv);
                P[r * 72 + j2]   = __float2bfloat16(e2 * inv);
            }
        }
        __syncthreads();

        // --- PV : 8 tiles, 1/warp ---
        {
            int mt = wid & 3, nt = wid >> 2;
            FC c;
            wmma::fill_fragment(c, 0.f);
#pragma unroll
            for (int k0 = 0; k0 < 64; k0 += 16) {
                FA a;
                wmma::load_matrix_sync(a, P + mt * 16 * 72 + k0, 72);
                FBr b;
                wmma::load_matrix_sync(b, vs + k0 * 40 + nt * 16, 40);
                wmma::mma_sync(c, a, b, c);
            }
            wmma::store_matrix_sync(pvbuf + mt * 16 * 40 + nt * 16, c, 40, wmma::mem_row_major);
        }
        __syncthreads();

        // convert PV fp32 -> o bf16 at this head's columns
        for (int idx = tid; idx < 64 * 32; idx += 256) {
            int r = idx >> 5, c = idx & 31;
            os[r * 200 + h * 32 + c] = __float2bfloat16(pvbuf[r * 40 + c]);
        }
        __syncthreads();
    }  // heads

    // --- proj: 48 tiles, warp = (mt, 6 n-tiles); epilogue in two fp32 phases ---
    {
        FC acc[6];
#pragma unroll
        for (int j = 0; j < 6; j++) wmma::fill_fragment(acc[j], 0.f);
        for (int k0 = 0; k0 < 192; k0 += 16) {
            FA a;
            wmma::load_matrix_sync(a, os + mtq * 16 * 200 + k0, 200);
#pragma unroll
            for (int j = 0; j < 6; j++) {
                int n0 = ngq * 96 + j * 16;
                FBc b;
                wmma::load_matrix_sync(b, g_wproj + n0 * 192 + k0, 192);
                wmma::mma_sync(acc[j], a, b, acc[j]);
            }
        }
#pragma unroll
        for (int p = 0; p < 2; p++) {
            __syncthreads();
            if (ngq == p) {
#pragma unroll
                for (int j = 0; j < 6; j++)
                    wmma::store_matrix_sync(fbuf + mtq * 16 * 100 + j * 16, acc[j],
                                            100, wmma::mem_row_major);
            }
            __syncthreads();
            for (int idx = tid; idx < 49 * 96; idx += 256) {
                int r = idx / 96, c = idx - r * 96;
                int gc = p * 96 + c;
                g_xres[win * 9408 + r * 192 + gc] = xw[r * 192 + gc] + fbuf[r * 100 + c] + bproj[gc];
            }
        }
    }
}

// ---------------------------------------------------------------------------
// Kernel B1: LN2 -> FC1 -> bias+GELU -> g_hmid (bf16)
// grid=3136 (64 rows/CTA), block=256 (8 warps), smem=52224 -> 2 CTAs/SM
// ---------------------------------------------------------------------------
#define F1_SM (25600 + 26624)

__global__ __launch_bounds__(256, 2) void fc1_kernel(
    const float* __restrict__ ln2g, const float* __restrict__ ln2b,
    const float* __restrict__ bfc1)
{
    extern __shared__ char smc[];
    bf16*  xn  = (bf16*)smc;              // 64x200 bf16
    float* buf = (float*)(smc + 25600);   // 64x104 f32

    const int tid = threadIdx.x;
    const int wid = tid >> 5;
    const int lane = tid & 31;
    const int row0 = blockIdx.x * 64;
    const float* xr = g_xres + (size_t)row0 * 192;

    // LN2 -> xn bf16
    for (int r = wid; r < 64; r += 8) {
        float v[6]; float s = 0.f;
#pragma unroll
        for (int j = 0; j < 6; j++) { v[j] = xr[r * 192 + j * 32 + lane]; s += v[j]; }
#pragma unroll
        for (int o = 16; o; o >>= 1) s += __shfl_xor_sync(0xffffffffu, s, o);
        float mu = s * (1.f / 192.f);
        float va = 0.f;
#pragma unroll
        for (int j = 0; j < 6; j++) { float d = v[j] - mu; va += d * d; }
#pragma unroll
        for (int o = 16; o; o >>= 1) va += __shfl_xor_sync(0xffffffffu, va, o);
        float rstd = rsqrtf(va * (1.f / 192.f) + LN_EPS);
#pragma unroll
        for (int j = 0; j < 6; j++) {
            int c = j * 32 + lane;
            xn[r * 200 + c] = __float2bfloat16((v[j] - mu) * rstd * ln2g[c] + ln2b[c]);
        }
    }
    __syncthreads();

    const int mt = wid & 1;       // row half (32 rows)
    const int nt = wid >> 1;      // 0..3 -> 48-col group

    for (int ch = 0; ch < 4; ch++) {
        FC acc[2][3];
#pragma unroll
        for (int s = 0; s < 2; s++)
#pragma unroll
            for (int j = 0; j < 3; j++) wmma::fill_fragment(acc[s][j], 0.f);

        for (int k0 = 0; k0 < 192; k0 += 16) {
            FA a0, a1;
            wmma::load_matrix_sync(a0, xn + (mt * 32) * 200 + k0, 200);
            wmma::load_matrix_sync(a1, xn + (mt * 32 + 16) * 200 + k0, 200);
#pragma unroll
            for (int j = 0; j < 3; j++) {
                int n0 = ch * 192 + nt * 48 + j * 16;
                FBc b;
                wmma::load_matrix_sync(b, g_wfc1 + n0 * 192 + k0, 192);
                wmma::mma_sync(acc[0][j], a0, b, acc[0][j]);
                wmma::mma_sync(acc[1][j], a1, b, acc[1][j]);
            }
        }

#pragma unroll
        for (int p = 0; p < 2; p++) {
            __syncthreads();
            if ((nt >> 1) == p) {
                int cl = (nt & 1) * 48;
#pragma unroll
                for (int s = 0; s < 2; s++)
#pragma unroll
                    for (int j = 0; j < 3; j++)
                        wmma::store_matrix_sync(buf + (mt * 32 + s * 16) * 104 + cl + j * 16,
                                                acc[s][j], 104, wmma::mem_row_major);
            }
            __syncthreads();
            for (int idx = tid; idx < 64 * 96; idx += 256) {
                int r = idx / 96, c = idx - r * 96;
                int gc = ch * 192 + p * 96 + c;
                float v = buf[r * 104 + c] + bfc1[gc];
                v = 0.5f * v * (1.f + erff(v * 0.70710678118654752f));
                g_hmid[(size_t)(row0 + r) * 768 + gc] = __float2bfloat16(v);
            }
        }
    }
}

// ---------------------------------------------------------------------------
// Kernel B2: FC2 -> +residual -> out
// grid=3136 (64 rows/CTA), block=256 (8 warps), smem=51200 -> 2 CTAs/SM
// ---------------------------------------------------------------------------
#define F2_SM (64 * 200 * 4)

__global__ __launch_bounds__(256, 2) void fc2_kernel(
    const float* __restrict__ bfc2, float* __restrict__ out)
{
    extern __shared__ float buf[];   // 64x200 f32

    const int tid = threadIdx.x;
    const int wid = tid >> 5;
    const int row0 = blockIdx.x * 64;
    const int mt = wid & 1;
    const int nt = wid >> 1;

    FC acc[2][3];
#pragma unroll
    for (int s = 0; s < 2; s++)
#pragma unroll
        for (int j = 0; j < 3; j++) wmma::fill_fragment(acc[s][j], 0.f);

    const bf16* hA = g_hmid + (size_t)row0 * 768;
    for (int k0 = 0; k0 < 768; k0 += 16) {
        FA a0, a1;
        wmma::load_matrix_sync(a0, hA + (size_t)(mt * 32) * 768 + k0, 768);
        wmma::load_matrix_sync(a1, hA + (size_t)(mt * 32 + 16) * 768 + k0, 768);
#pragma unroll
        for (int j = 0; j < 3; j++) {
            int n0 = nt * 48 + j * 16;
            FBc b;
            wmma::load_matrix_sync(b, g_wfc2 + n0 * 768 + k0, 768);
            wmma::mma_sync(acc[0][j], a0, b, acc[0][j]);
            wmma::mma_sync(acc[1][j], a1, b, acc[1][j]);
        }
    }

#pragma unroll
    for (int s = 0; s < 2; s++)
#pragma unroll
        for (int j = 0; j < 3; j++)
            wmma::store_matrix_sync(buf + (mt * 32 + s * 16) * 200 + nt * 48 + j * 16,
                                    acc[s][j], 200, wmma::mem_row_major);
    __syncthreads();

    const float* xr = g_xres + (size_t)row0 * 192;
    for (int idx = tid; idx < 64 * 192; idx += 256) {
        int r = idx / 192, c = idx - r * 192;
        out[(size_t)row0 * 192 + idx] = xr[idx] + buf[r * 200 + c] + bfc2[c];
    }
}

// ---------------------------------------------------------------------------

extern "C" void kernel_launch(void* const* d_in, const int* in_sizes, int n_in,
                              void* d_out, int out_size)
{
    const float* x     = (const float*)d_in[0];
    const int*   msk   = (const int*)  d_in[1];
    const float* ln1g  = (const float*)d_in[2];
    const float* ln1b  = (const float*)d_in[3];
    const float* wqkv  = (const float*)d_in[4];
    const float* bqkv  = (const float*)d_in[5];
    const float* wproj = (const float*)d_in[6];
    const float* bproj = (const float*)d_in[7];
    const float* ln2g  = (const float*)d_in[8];
    const float* ln2b  = (const float*)d_in[9];
    const float* wfc1  = (const float*)d_in[10];
    const float* bfc1  = (const float*)d_in[11];
    const float* wfc2  = (const float*)d_in[12];
    const float* bfc2  = (const float*)d_in[13];
    float* out = (float*)d_out;

    cudaFuncSetAttribute(attn_kernel, cudaFuncAttributeMaxDynamicSharedMemorySize, AT_SM);
    cudaFuncSetAttribute(fc1_kernel,  cudaFuncAttributeMaxDynamicSharedMemorySize, F1_SM);
    cudaFuncSetAttribute(fc2_kernel,  cudaFuncAttributeMaxDynamicSharedMemorySize, F2_SM);

    cvt_all<<<576, 256>>>(wqkv, wproj, wfc1, wfc2);
    attn_kernel<<<4096, 256, AT_SM>>>(x, msk, ln1g, ln1b, bqkv, bproj);
    fc1_kernel<<<3136, 256, F1_SM>>>(ln2g, ln2b, bfc1);
    fc2_kernel<<<3136, 256, F2_SM>>>(bfc2, out);
}

// round 3
// speedup vs baseline: 4.7301x; 1.6428x over previous
#include <cuda_runtime.h>
#include <cuda_bf16.h>
#include <mma.h>
#include <math.h>

using namespace nvcuda;
typedef __nv_bfloat16 bf16;

#define LN_EPS 1e-5f

// persistent scratch (device globals: allocation-free)
__device__ float g_xres[(size_t)200704 * 192];        // mid residual
__device__ bf16  g_qkv [(size_t)200704 * 576];        // LN1 @ Wqkv^T + b
__device__ bf16  g_attno[(size_t)200704 * 192];       // attention output (pre-proj)
__device__ bf16  g_hmid[(size_t)200704 * 768];        // GELU(fc1)
__device__ bf16  g_wqkv[576 * 192];
__device__ bf16  g_wproj[192 * 192];
__device__ bf16  g_wfc1[768 * 192];
__device__ bf16  g_wfc2[192 * 768];

typedef wmma::fragment<wmma::matrix_a, 16, 16, 16, bf16, wmma::row_major> FA;
typedef wmma::fragment<wmma::matrix_b, 16, 16, 16, bf16, wmma::col_major> FBc;
typedef wmma::fragment<wmma::matrix_b, 16, 16, 16, bf16, wmma::row_major> FBr;
typedef wmma::fragment<wmma::accumulator, 16, 16, 16, float> FC;

// ---------------------------------------------------------------------------
__global__ void cvt_all(const float* __restrict__ wqkv, const float* __restrict__ wproj,
                        const float* __restrict__ wfc1, const float* __restrict__ wfc2)
{
    int i = blockIdx.x * 256 + threadIdx.x;
    if (i < 110592) g_wqkv[i]  = __float2bfloat16(wqkv[i]);
    if (i < 36864)  g_wproj[i] = __float2bfloat16(wproj[i]);
    if (i < 147456) {
        g_wfc1[i] = __float2bfloat16(wfc1[i]);
        g_wfc2[i] = __float2bfloat16(wfc2[i]);
    }
}

// ---------------------------------------------------------------------------
// Shared GEMM helpers: CTA = 128 rows x 192-col pass, block 512 (16 warps),
// warp = 32 rows x 48 cols (6 acc frags). A ld = 200, B ld = 200 (bf16).
// smem: As 51200 B | Bs 76800 B (fp32 epilogue buf 128x104 aliases Bs)
// ---------------------------------------------------------------------------
#define GEMM_SM (51200 + 76800)

__device__ __forceinline__ void stage_B192(bf16* Bs, const bf16* __restrict__ src,
                                           int src_stride, int tid)
{
    for (int idx = tid; idx < 192 * 24; idx += 512) {
        int r = idx / 24, c8 = (idx - r * 24) * 8;
        *(uint4*)(Bs + r * 200 + c8) = *(const uint4*)(src + (size_t)r * src_stride + c8);
    }
}

__device__ __forceinline__ void stage_A_bf16(bf16* As, const bf16* __restrict__ src,
                                             int src_stride, int tid)
{
    for (int idx = tid; idx < 128 * 24; idx += 512) {
        int r = idx / 24, c8 = (idx - r * 24) * 8;
        *(uint4*)(As + r * 200 + c8) = *(const uint4*)(src + (size_t)r * src_stride + c8);
    }
}

__device__ __forceinline__ void stage_A_ln(bf16* As, const float* __restrict__ xr,
                                           const float* __restrict__ g,
                                           const float* __restrict__ b,
                                           int wid, int lane)
{
    for (int r = wid; r < 128; r += 16) {
        float v[6]; float s = 0.f;
#pragma unroll
        for (int j = 0; j < 6; j++) { v[j] = xr[r * 192 + j * 32 + lane]; s += v[j]; }
#pragma unroll
        for (int o = 16; o; o >>= 1) s += __shfl_xor_sync(0xffffffffu, s, o);
        float mu = s * (1.f / 192.f);
        float va = 0.f;
#pragma unroll
        for (int j = 0; j < 6; j++) { float d = v[j] - mu; va += d * d; }
#pragma unroll
        for (int o = 16; o; o >>= 1) va += __shfl_xor_sync(0xffffffffu, va, o);
        float rstd = rsqrtf(va * (1.f / 192.f) + LN_EPS);
#pragma unroll
        for (int j = 0; j < 6; j++) {
            int c = j * 32 + lane;
            As[r * 200 + c] = __float2bfloat16((v[j] - mu) * rstd * g[c] + b[c]);
        }
    }
}

__device__ __forceinline__ void mma_pass(const bf16* As, const bf16* Bs,
                                         int mt, int ng, FC acc[6])
{
#pragma unroll 4
    for (int k0 = 0; k0 < 192; k0 += 16) {
        FA a0, a1;
        wmma::load_matrix_sync(a0, As + (mt * 32) * 200 + k0, 200);
        wmma::load_matrix_sync(a1, As + (mt * 32 + 16) * 200 + k0, 200);
#pragma unroll
        for (int j = 0; j < 3; j++) {
            FBc b;
            wmma::load_matrix_sync(b, Bs + (ng * 48 + j * 16) * 200 + k0, 200);
            wmma::mma_sync(acc[j],     a0, b, acc[j]);
            wmma::mma_sync(acc[j + 3], a1, b, acc[j + 3]);
        }
    }
}

__device__ __forceinline__ void epi_store(float* buf, int mt, int ng, int ph, FC acc[6])
{
    if ((ng >> 1) == ph) {
        int cl = (ng & 1) * 48;
#pragma unroll
        for (int j = 0; j < 3; j++) {
            wmma::store_matrix_sync(buf + (mt * 32) * 104 + cl + j * 16,      acc[j],     104, wmma::mem_row_major);
            wmma::store_matrix_sync(buf + (mt * 32 + 16) * 104 + cl + j * 16, acc[j + 3], 104, wmma::mem_row_major);
        }
    }
}

// ---------------------------------------------------------------------------
// Kernel 1: LN1 -> QKV GEMM (N=576 in 3 passes) -> g_qkv bf16
// ---------------------------------------------------------------------------
__global__ __launch_bounds__(512, 1) void qkv_kernel(
    const float* __restrict__ x, const float* __restrict__ ln1g,
    const float* __restrict__ ln1b, const float* __restrict__ bqkv)
{
    extern __shared__ char smc[];
    bf16*  As  = (bf16*)smc;
    bf16*  Bs  = (bf16*)(smc + 51200);
    float* buf = (float*)(smc + 51200);

    const int tid = threadIdx.x, wid = tid >> 5, lane = tid & 31;
    const int row0 = blockIdx.x * 128;
    const int mt = wid & 3, ng = wid >> 2;

    stage_A_ln(As, x + (size_t)row0 * 192, ln1g, ln1b, wid, lane);

    for (int p = 0; p < 3; p++) {
        __syncthreads();
        stage_B192(Bs, g_wqkv + p * 192 * 192, 192, tid);
        __syncthreads();
        FC acc[6];
#pragma unroll
        for (int j = 0; j < 6; j++) wmma::fill_fragment(acc[j], 0.f);
        mma_pass(As, Bs, mt, ng, acc);
#pragma unroll
        for (int ph = 0; ph < 2; ph++) {
            __syncthreads();
            epi_store(buf, mt, ng, ph, acc);
            __syncthreads();
            for (int idx = tid; idx < 128 * 96; idx += 512) {
                int r = idx / 96, c = idx - r * 96;
                int gc = p * 192 + ph * 96 + c;
                g_qkv[(size_t)(row0 + r) * 576 + gc] = __float2bfloat16(buf[r * 104 + c] + bqkv[gc]);
            }
        }
    }
}

// ---------------------------------------------------------------------------
// Kernel 2: attention core per (window, head): S -> masked softmax -> PV
// grid = (4096, 6), block = 256 (8 warps), smem = 41984 B
// ---------------------------------------------------------------------------
#define AT_SM 41984

__global__ __launch_bounds__(256) void attn_core(const int* __restrict__ mask)
{
    extern __shared__ char smc[];
    bf16*  qs    = (bf16*)smc;               // 64x40
    bf16*  ks    = (bf16*)(smc + 5120);      // 64x40
    bf16*  vs    = (bf16*)(smc + 10240);     // 64x40
    float* S     = (float*)(smc + 15360);    // 64x68 f32
    bf16*  P     = (bf16*)(smc + 32768);     // 64x72
    float* pvbuf = (float*)(smc + 15360);    // alias S

    const int tid = threadIdx.x, wid = tid >> 5, lane = tid & 31;
    const int win = blockIdx.x, h = blockIdx.y;
    const size_t base = (size_t)(win * 49) * 576;

    // load q,k,v head slices (zero-pad rows 49..63); 256 thr == 64 rows x 4 chunks
    {
        const int r = tid >> 2, c8 = (tid & 3) * 8;
        uint4 z; z.x = z.y = z.z = z.w = 0u;
#pragma unroll
        for (int m = 0; m < 3; m++) {
            bf16* dst = (m == 0) ? qs : ((m == 1) ? ks : vs);
            uint4 val = z;
            if (r < 49)
                val = *(const uint4*)(g_qkv + base + (size_t)r * 576 + m * 192 + h * 32 + c8);
            *(uint4*)(dst + r * 40 + c8) = val;
        }
    }
    __syncthreads();

    // S = q k^T : 16 tiles, 2/warp
#pragma unroll
    for (int it = 0; it < 2; it++) {
        int t = wid + it * 8;
        int mt = t & 3, nt = t >> 2;
        FC c;
        wmma::fill_fragment(c, 0.f);
#pragma unroll
        for (int k0 = 0; k0 < 32; k0 += 16) {
            FA a;
            wmma::load_matrix_sync(a, qs + mt * 16 * 40 + k0, 40);
            FBc b;
            wmma::load_matrix_sync(b, ks + nt * 16 * 40 + k0, 40);
            wmma::mma_sync(c, a, b, c);
        }
        wmma::store_matrix_sync(S + mt * 16 * 68 + nt * 16, c, 68, wmma::mem_row_major);
    }
    __syncthreads();

    // masked softmax (fp32) -> P bf16
    {
        const float scale = 0.17677669529663687f;
        const int* mrow_base = mask + (size_t)win * 49 * 49;
        for (int r = wid; r < 49; r += 8) {
            const int* mrow = mrow_base + r * 49;
            int j2 = lane + 32;
            float s1 = (mrow[lane] == 0) ? -1e30f : S[r * 68 + lane] * scale;
            float s2 = (j2 < 49 && mrow[j2] != 0) ? S[r * 68 + j2] * scale : -1e30f;
            float m = fmaxf(s1, s2);
#pragma unroll
            for (int o = 16; o; o >>= 1) m = fmaxf(m, __shfl_xor_sync(0xffffffffu, m, o));
            float e1 = __expf(s1 - m);
            float e2 = (j2 < 49) ? __expf(s2 - m) : 0.f;
            float sum = e1 + e2;
#pragma unroll
            for (int o = 16; o; o >>= 1) sum += __shfl_xor_sync(0xffffffffu, sum, o);
            float inv = 1.f / sum;
            P[r * 72 + lane] = __float2bfloat16(e1 * inv);
            P[r * 72 + j2]   = __float2bfloat16(e2 * inv);
        }
    }
    __syncthreads();

    // PV : 8 tiles, 1/warp
    {
        int mt = wid & 3, nt = wid >> 2;
        FC c;
        wmma::fill_fragment(c, 0.f);
#pragma unroll
        for (int k0 = 0; k0 < 64; k0 += 16) {
            FA a;
            wmma::load_matrix_sync(a, P + mt * 16 * 72 + k0, 72);
            FBr b;
            wmma::load_matrix_sync(b, vs + k0 * 40 + nt * 16, 40);
            wmma::mma_sync(c, a, b, c);
        }
        wmma::store_matrix_sync(pvbuf + mt * 16 * 40 + nt * 16, c, 40, wmma::mem_row_major);
    }
    __syncthreads();

    for (int idx = tid; idx < 49 * 32; idx += 256) {
        int r = idx >> 5, c = idx & 31;
        g_attno[(size_t)(win * 49 + r) * 192 + h * 32 + c] = __float2bfloat16(pvbuf[r * 40 + c]);
    }
}

// ---------------------------------------------------------------------------
// Kernel 3: proj GEMM (N=192) + residual -> g_xres (f32)
// ---------------------------------------------------------------------------
__global__ __launch_bounds__(512, 1) void proj_kernel(
    const float* __restrict__ x, const float* __restrict__ bproj)
{
    extern __shared__ char smc[];
    bf16*  As  = (bf16*)smc;
    bf16*  Bs  = (bf16*)(smc + 51200);
    float* buf = (float*)(smc + 51200);

    const int tid = threadIdx.x, wid = tid >> 5;
    const int row0 = blockIdx.x * 128;
    const int mt = wid & 3, ng = wid >> 2;

    stage_A_bf16(As, g_attno + (size_t)row0 * 192, 192, tid);
    stage_B192(Bs, g_wproj, 192, tid);
    __syncthreads();

    FC acc[6];
#pragma unroll
    for (int j = 0; j < 6; j++) wmma::fill_fragment(acc[j], 0.f);
    mma_pass(As, Bs, mt, ng, acc);

#pragma unroll
    for (int ph = 0; ph < 2; ph++) {
        __syncthreads();
        epi_store(buf, mt, ng, ph, acc);
        __syncthreads();
        for (int idx = tid; idx < 128 * 96; idx += 512) {
            int r = idx / 96, c = idx - r * 96;
            int gc = ph * 96 + c;
            size_t gi = (size_t)(row0 + r) * 192 + gc;
            g_xres[gi] = x[gi] + buf[r * 104 + c] + bproj[gc];
        }
    }
}

// ---------------------------------------------------------------------------
// Kernel 4: LN2 -> FC1 GEMM (N=768 in 4 passes) -> bias+GELU -> g_hmid bf16
// ---------------------------------------------------------------------------
__global__ __launch_bounds__(512, 1) void fc1_kernel(
    const float* __restrict__ ln2g, const float* __restrict__ ln2b,
    const float* __restrict__ bfc1)
{
    extern __shared__ char smc[];
    bf16*  As  = (bf16*)smc;
    bf16*  Bs  = (bf16*)(smc + 51200);
    float* buf = (float*)(smc + 51200);

    const int tid = threadIdx.x, wid = tid >> 5, lane = tid & 31;
    const int row0 = blockIdx.x * 128;
    const int mt = wid & 3, ng = wid >> 2;

    stage_A_ln(As, g_xres + (size_t)row0 * 192, ln2g, ln2b, wid, lane);

    for (int p = 0; p < 4; p++) {
        __syncthreads();
        stage_B192(Bs, g_wfc1 + p * 192 * 192, 192, tid);
        __syncthreads();
        FC acc[6];
#pragma unroll
        for (int j = 0; j < 6; j++) wmma::fill_fragment(acc[j], 0.f);
        mma_pass(As, Bs, mt, ng, acc);
#pragma unroll
        for (int ph = 0; ph < 2; ph++) {
            __syncthreads();
            epi_store(buf, mt, ng, ph, acc);
            __syncthreads();
            for (int idx = tid; idx < 128 * 96; idx += 512) {
                int r = idx / 96, c = idx - r * 96;
                int gc = p * 192 + ph * 96 + c;
                float v = buf[r * 104 + c] + bfc1[gc];
                v = 0.5f * v * (1.f + erff(v * 0.70710678118654752f));
                g_hmid[(size_t)(row0 + r) * 768 + gc] = __float2bfloat16(v);
            }
        }
    }
}

// ---------------------------------------------------------------------------
// Kernel 5: FC2 GEMM (K=768 in 4 staged chunks, persistent acc) + residual -> out
// ---------------------------------------------------------------------------
__global__ __launch_bounds__(512, 1) void fc2_kernel(
    const float* __restrict__ bfc2, float* __restrict__ out)
{
    extern __shared__ char smc[];
    bf16*  As  = (bf16*)smc;
    bf16*  Bs  = (bf16*)(smc + 51200);
    float* buf = (float*)(smc + 51200);

    const int tid = threadIdx.x, wid = tid >> 5;
    const int row0 = blockIdx.x * 128;
    const int mt = wid & 3, ng = wid >> 2;

    FC acc[6];
#pragma unroll
    for (int j = 0; j < 6; j++) wmma::fill_fragment(acc[j], 0.f);

    for (int kc = 0; kc < 4; kc++) {
        __syncthreads();
        stage_A_bf16(As, g_hmid + (size_t)row0 * 768 + kc * 192, 768, tid);
        stage_B192(Bs, g_wfc2 + kc * 192, 768, tid);
        __syncthreads();
        mma_pass(As, Bs, mt, ng, acc);
    }

#pragma unroll
    for (int ph = 0; ph < 2; ph++) {
        __syncthreads();
        epi_store(buf, mt, ng, ph, acc);
        __syncthreads();
        for (int idx = tid; idx < 128 * 96; idx += 512) {
            int r = idx / 96, c = idx - r * 96;
            int gc = ph * 96 + c;
            size_t gi = (size_t)(row0 + r) * 192 + gc;
            out[gi] = g_xres[gi] + buf[r * 104 + c] + bfc2[gc];
        }
    }
}

// ---------------------------------------------------------------------------

extern "C" void kernel_launch(void* const* d_in, const int* in_sizes, int n_in,
                              void* d_out, int out_size)
{
    const float* x     = (const float*)d_in[0];
    const int*   msk   = (const int*)  d_in[1];
    const float* ln1g  = (const float*)d_in[2];
    const float* ln1b  = (const float*)d_in[3];
    const float* wqkv  = (const float*)d_in[4];
    const float* bqkv  = (const float*)d_in[5];
    const float* wproj = (const float*)d_in[6];
    const float* bproj = (const float*)d_in[7];
    const float* ln2g  = (const float*)d_in[8];
    const float* ln2b  = (const float*)d_in[9];
    const float* wfc1  = (const float*)d_in[10];
    const float* bfc1  = (const float*)d_in[11];
    const float* wfc2  = (const float*)d_in[12];
    const float* bfc2  = (const float*)d_in[13];
    float* out = (float*)d_out;

    cudaFuncSetAttribute(qkv_kernel,  cudaFuncAttributeMaxDynamicSharedMemorySize, GEMM_SM);
    cudaFuncSetAttribute(attn_core,   cudaFuncAttributeMaxDynamicSharedMemorySize, AT_SM);
    cudaFuncSetAttribute(proj_kernel, cudaFuncAttributeMaxDynamicSharedMemorySize, GEMM_SM);
    cudaFuncSetAttribute(fc1_kernel,  cudaFuncAttributeMaxDynamicSharedMemorySize, GEMM_SM);
    cudaFuncSetAttribute(fc2_kernel,  cudaFuncAttributeMaxDynamicSharedMemorySize, GEMM_SM);

    cvt_all<<<576, 256>>>(wqkv, wproj, wfc1, wfc2);
    qkv_kernel<<<1568, 512, GEMM_SM>>>(x, ln1g, ln1b, bqkv);
    attn_core<<<dim3(4096, 6), 256, AT_SM>>>(msk);
    proj_kernel<<<1568, 512, GEMM_SM>>>(x, bproj);
    fc1_kernel<<<1568, 512, GEMM_SM>>>(ln2g, ln2b, bfc1);
    fc2_kernel<<<1568, 512, GEMM_SM>>>(bfc2, out);
}

// round 4
// speedup vs baseline: 5.2108x; 1.1016x over previous
#include <cuda_runtime.h>
#include <cuda_bf16.h>
#include <mma.h>
#include <math.h>

using namespace nvcuda;
typedef __nv_bfloat16 bf16;

#define LN_EPS 1e-5f

// persistent scratch (device globals: allocation-free)
__device__ float g_xres[(size_t)200704 * 192];        // mid residual
__device__ bf16  g_qkv [(size_t)200704 * 576];        // LN1 @ Wqkv^T + b
__device__ bf16  g_attno[(size_t)200704 * 192];       // attention output (pre-proj)
__device__ bf16  g_hmid[(size_t)200704 * 768];        // GELU(fc1)
__device__ bf16  g_wqkv[576 * 192];
__device__ bf16  g_wproj[192 * 192];
__device__ bf16  g_wfc1[768 * 192];
__device__ bf16  g_wfc2[192 * 768];

typedef wmma::fragment<wmma::matrix_a, 16, 16, 16, bf16, wmma::row_major> FA;
typedef wmma::fragment<wmma::matrix_b, 16, 16, 16, bf16, wmma::col_major> FBc;
typedef wmma::fragment<wmma::matrix_b, 16, 16, 16, bf16, wmma::row_major> FBr;
typedef wmma::fragment<wmma::accumulator, 16, 16, 16, float> FC;

// ---------------------------------------------------------------------------
__global__ void cvt_all(const float* __restrict__ wqkv, const float* __restrict__ wproj,
                        const float* __restrict__ wfc1, const float* __restrict__ wfc2)
{
    int i = blockIdx.x * 256 + threadIdx.x;
    if (i < 110592) g_wqkv[i]  = __float2bfloat16(wqkv[i]);
    if (i < 36864)  g_wproj[i] = __float2bfloat16(wproj[i]);
    if (i < 147456) {
        g_wfc1[i] = __float2bfloat16(wfc1[i]);
        g_wfc2[i] = __float2bfloat16(wfc2[i]);
    }
}

// ---------------------------------------------------------------------------
// GEMM core: block 256 (8 warps), CTA = 128 rows; N processed in 96-col slices.
// warp tile = 32 rows x 48 cols (6 acc frags): mt = wid&3, ng = wid>>2.
// smem: As 128x200 bf16 (51200) | Bs 96x200 bf16 (38400, fp32 epi buf aliases)
// 89600 B total -> 2 CTAs/SM.
// ---------------------------------------------------------------------------
#define GEMM_SM (51200 + 38400)

__device__ __forceinline__ void stage_B96(bf16* Bs, const bf16* __restrict__ src,
                                          int src_stride, int tid)
{
    for (int idx = tid; idx < 96 * 24; idx += 256) {
        int r = idx / 24, c8 = (idx - r * 24) * 8;
        *(uint4*)(Bs + r * 200 + c8) = *(const uint4*)(src + (size_t)r * src_stride + c8);
    }
}

__device__ __forceinline__ void stage_A_bf16(bf16* As, const bf16* __restrict__ src,
                                             int src_stride, int tid)
{
    for (int idx = tid; idx < 128 * 24; idx += 256) {
        int r = idx / 24, c8 = (idx - r * 24) * 8;
        *(uint4*)(As + r * 200 + c8) = *(const uint4*)(src + (size_t)r * src_stride + c8);
    }
}

__device__ __forceinline__ void stage_A_ln(bf16* As, const float* __restrict__ xr,
                                           const float* __restrict__ g,
                                           const float* __restrict__ b,
                                           int wid, int lane)
{
    for (int r = wid; r < 128; r += 8) {
        float v[6]; float s = 0.f;
#pragma unroll
        for (int j = 0; j < 6; j++) { v[j] = xr[r * 192 + j * 32 + lane]; s += v[j]; }
#pragma unroll
        for (int o = 16; o; o >>= 1) s += __shfl_xor_sync(0xffffffffu, s, o);
        float mu = s * (1.f / 192.f);
        float va = 0.f;
#pragma unroll
        for (int j = 0; j < 6; j++) { float d = v[j] - mu; va += d * d; }
#pragma unroll
        for (int o = 16; o; o >>= 1) va += __shfl_xor_sync(0xffffffffu, va, o);
        float rstd = rsqrtf(va * (1.f / 192.f) + LN_EPS);
#pragma unroll
        for (int j = 0; j < 6; j++) {
            int c = j * 32 + lane;
            As[r * 200 + c] = __float2bfloat16((v[j] - mu) * rstd * g[c] + b[c]);
        }
    }
}

__device__ __forceinline__ void mma_pass96(const bf16* As, const bf16* Bs,
                                           int mt, int ng, FC acc[6])
{
#pragma unroll 4
    for (int k0 = 0; k0 < 192; k0 += 16) {
        FA a0, a1;
        wmma::load_matrix_sync(a0, As + (mt * 32) * 200 + k0, 200);
        wmma::load_matrix_sync(a1, As + (mt * 32 + 16) * 200 + k0, 200);
#pragma unroll
        for (int j = 0; j < 3; j++) {
            FBc b;
            wmma::load_matrix_sync(b, Bs + (ng * 48 + j * 16) * 200 + k0, 200);
            wmma::mma_sync(acc[j],     a0, b, acc[j]);
            wmma::mma_sync(acc[j + 3], a1, b, acc[j + 3]);
        }
    }
}

// epilogue phase: warps with ng==ph dump their 48 cols into fp32 buf (ld 52)
__device__ __forceinline__ void epi_store48(float* buf, int mt, int ng, int ph, FC acc[6])
{
    if (ng == ph) {
#pragma unroll
        for (int j = 0; j < 3; j++) {
            wmma::store_matrix_sync(buf + (mt * 32) * 52 + j * 16,      acc[j],     52, wmma::mem_row_major);
            wmma::store_matrix_sync(buf + (mt * 32 + 16) * 52 + j * 16, acc[j + 3], 52, wmma::mem_row_major);
        }
    }
}

// ---------------------------------------------------------------------------
// Kernel 1: LN1 -> QKV GEMM (N=576 in 6 slices) -> g_qkv bf16
// ---------------------------------------------------------------------------
__global__ __launch_bounds__(256, 2) void qkv_kernel(
    const float* __restrict__ x, const float* __restrict__ ln1g,
    const float* __restrict__ ln1b, const float* __restrict__ bqkv)
{
    extern __shared__ char smc[];
    bf16*  As  = (bf16*)smc;
    bf16*  Bs  = (bf16*)(smc + 51200);
    float* buf = (float*)(smc + 51200);

    const int tid = threadIdx.x, wid = tid >> 5, lane = tid & 31;
    const int row0 = blockIdx.x * 128;
    const int mt = wid & 3, ng = wid >> 2;

    stage_A_ln(As, x + (size_t)row0 * 192, ln1g, ln1b, wid, lane);

    for (int p = 0; p < 6; p++) {
        __syncthreads();
        stage_B96(Bs, g_wqkv + p * 96 * 192, 192, tid);
        __syncthreads();
        FC acc[6];
#pragma unroll
        for (int j = 0; j < 6; j++) wmma::fill_fragment(acc[j], 0.f);
        mma_pass96(As, Bs, mt, ng, acc);
#pragma unroll
        for (int ph = 0; ph < 2; ph++) {
            __syncthreads();
            epi_store48(buf, mt, ng, ph, acc);
            __syncthreads();
            for (int idx = tid; idx < 128 * 48; idx += 256) {
                int r = idx / 48, c = idx - r * 48;
                int gc = p * 96 + ph * 48 + c;
                g_qkv[(size_t)(row0 + r) * 576 + gc] = __float2bfloat16(buf[r * 52 + c] + bqkv[gc]);
            }
        }
    }
}

// ---------------------------------------------------------------------------
// Kernel 2: attention core per (window, head): S -> masked softmax -> PV
// grid = (4096, 6), block = 256 (8 warps), smem = 41984 B
// ---------------------------------------------------------------------------
#define AT_SM 41984

__global__ __launch_bounds__(256) void attn_core(const int* __restrict__ mask)
{
    extern __shared__ char smc[];
    bf16*  qs    = (bf16*)smc;               // 64x40
    bf16*  ks    = (bf16*)(smc + 5120);      // 64x40
    bf16*  vs    = (bf16*)(smc + 10240);     // 64x40
    float* S     = (float*)(smc + 15360);    // 64x68 f32
    bf16*  P     = (bf16*)(smc + 32768);     // 64x72
    float* pvbuf = (float*)(smc + 15360);    // alias S

    const int tid = threadIdx.x, wid = tid >> 5, lane = tid & 31;
    const int win = blockIdx.x, h = blockIdx.y;
    const size_t base = (size_t)(win * 49) * 576;

    {
        const int r = tid >> 2, c8 = (tid & 3) * 8;
        uint4 z; z.x = z.y = z.z = z.w = 0u;
#pragma unroll
        for (int m = 0; m < 3; m++) {
            bf16* dst = (m == 0) ? qs : ((m == 1) ? ks : vs);
            uint4 val = z;
            if (r < 49)
                val = *(const uint4*)(g_qkv + base + (size_t)r * 576 + m * 192 + h * 32 + c8);
            *(uint4*)(dst + r * 40 + c8) = val;
        }
    }
    __syncthreads();

    // S = q k^T : 16 tiles, 2/warp
#pragma unroll
    for (int it = 0; it < 2; it++) {
        int t = wid + it * 8;
        int mt = t & 3, nt = t >> 2;
        FC c;
        wmma::fill_fragment(c, 0.f);
#pragma unroll
        for (int k0 = 0; k0 < 32; k0 += 16) {
            FA a;
            wmma::load_matrix_sync(a, qs + mt * 16 * 40 + k0, 40);
            FBc b;
            wmma::load_matrix_sync(b, ks + nt * 16 * 40 + k0, 40);
            wmma::mma_sync(c, a, b, c);
        }
        wmma::store_matrix_sync(S + mt * 16 * 68 + nt * 16, c, 68, wmma::mem_row_major);
    }
    __syncthreads();

    // masked softmax (fp32) -> P bf16
    {
        const float scale = 0.17677669529663687f;
        const int* mrow_base = mask + (size_t)win * 49 * 49;
        for (int r = wid; r < 49; r += 8) {
            const int* mrow = mrow_base + r * 49;
            int j2 = lane + 32;
            float s1 = (mrow[lane] == 0) ? -1e30f : S[r * 68 + lane] * scale;
            float s2 = (j2 < 49 && mrow[j2] != 0) ? S[r * 68 + j2] * scale : -1e30f;
            float m = fmaxf(s1, s2);
#pragma unroll
            for (int o = 16; o; o >>= 1) m = fmaxf(m, __shfl_xor_sync(0xffffffffu, m, o));
            float e1 = __expf(s1 - m);
            float e2 = (j2 < 49) ? __expf(s2 - m) : 0.f;
            float sum = e1 + e2;
#pragma unroll
            for (int o = 16; o; o >>= 1) sum += __shfl_xor_sync(0xffffffffu, sum, o);
            float inv = 1.f / sum;
            P[r * 72 + lane] = __float2bfloat16(e1 * inv);
            P[r * 72 + j2]   = __float2bfloat16(e2 * inv);
        }
    }
    __syncthreads();

    // PV : 8 tiles, 1/warp
    {
        int mt = wid & 3, nt = wid >> 2;
        FC c;
        wmma::fill_fragment(c, 0.f);
#pragma unroll
        for (int k0 = 0; k0 < 64; k0 += 16) {
            FA a;
            wmma::load_matrix_sync(a, P + mt * 16 * 72 + k0, 72);
            FBr b;
            wmma::load_matrix_sync(b, vs + k0 * 40 + nt * 16, 40);
            wmma::mma_sync(c, a, b, c);
        }
        wmma::store_matrix_sync(pvbuf + mt * 16 * 40 + nt * 16, c, 40, wmma::mem_row_major);
    }
    __syncthreads();

    for (int idx = tid; idx < 49 * 32; idx += 256) {
        int r = idx >> 5, c = idx & 31;
        g_attno[(size_t)(win * 49 + r) * 192 + h * 32 + c] = __float2bfloat16(pvbuf[r * 40 + c]);
    }
}

// ---------------------------------------------------------------------------
// Kernel 3: proj GEMM (N=192 in 2 slices) + residual -> g_xres (f32)
// ---------------------------------------------------------------------------
__global__ __launch_bounds__(256, 2) void proj_kernel(
    const float* __restrict__ x, const float* __restrict__ bproj)
{
    extern __shared__ char smc[];
    bf16*  As  = (bf16*)smc;
    bf16*  Bs  = (bf16*)(smc + 51200);
    float* buf = (float*)(smc + 51200);

    const int tid = threadIdx.x, wid = tid >> 5;
    const int row0 = blockIdx.x * 128;
    const int mt = wid & 3, ng = wid >> 2;

    stage_A_bf16(As, g_attno + (size_t)row0 * 192, 192, tid);

    for (int p = 0; p < 2; p++) {
        __syncthreads();
        stage_B96(Bs, g_wproj + p * 96 * 192, 192, tid);
        __syncthreads();
        FC acc[6];
#pragma unroll
        for (int j = 0; j < 6; j++) wmma::fill_fragment(acc[j], 0.f);
        mma_pass96(As, Bs, mt, ng, acc);
#pragma unroll
        for (int ph = 0; ph < 2; ph++) {
            __syncthreads();
            epi_store48(buf, mt, ng, ph, acc);
            __syncthreads();
            for (int idx = tid; idx < 128 * 48; idx += 256) {
                int r = idx / 48, c = idx - r * 48;
                int gc = p * 96 + ph * 48 + c;
                size_t gi = (size_t)(row0 + r) * 192 + gc;
                g_xres[gi] = x[gi] + buf[r * 52 + c] + bproj[gc];
            }
        }
    }
}

// ---------------------------------------------------------------------------
// Kernel 4: LN2 -> FC1 GEMM (N=768 in 8 slices) -> bias+GELU -> g_hmid bf16
// ---------------------------------------------------------------------------
__global__ __launch_bounds__(256, 2) void fc1_kernel(
    const float* __restrict__ ln2g, const float* __restrict__ ln2b,
    const float* __restrict__ bfc1)
{
    extern __shared__ char smc[];
    bf16*  As  = (bf16*)smc;
    bf16*  Bs  = (bf16*)(smc + 51200);
    float* buf = (float*)(smc + 51200);

    const int tid = threadIdx.x, wid = tid >> 5, lane = tid & 31;
    const int row0 = blockIdx.x * 128;
    const int mt = wid & 3, ng = wid >> 2;

    stage_A_ln(As, g_xres + (size_t)row0 * 192, ln2g, ln2b, wid, lane);

    for (int p = 0; p < 8; p++) {
        __syncthreads();
        stage_B96(Bs, g_wfc1 + p * 96 * 192, 192, tid);
        __syncthreads();
        FC acc[6];
#pragma unroll
        for (int j = 0; j < 6; j++) wmma::fill_fragment(acc[j], 0.f);
        mma_pass96(As, Bs, mt, ng, acc);
#pragma unroll
        for (int ph = 0; ph < 2; ph++) {
            __syncthreads();
            epi_store48(buf, mt, ng, ph, acc);
            __syncthreads();
            for (int idx = tid; idx < 128 * 48; idx += 256) {
                int r = idx / 48, c = idx - r * 48;
                int gc = p * 96 + ph * 48 + c;
                float v = buf[r * 52 + c] + bfc1[gc];
                v = 0.5f * v * (1.f + erff(v * 0.70710678118654752f));
                g_hmid[(size_t)(row0 + r) * 768 + gc] = __float2bfloat16(v);
            }
        }
    }
}

// ---------------------------------------------------------------------------
// Kernel 5: FC2 GEMM. grid (1568, 2): y = 96-col slice. K=768 in 4 chunks,
// persistent acc; + residual -> out
// ---------------------------------------------------------------------------
__global__ __launch_bounds__(256, 2) void fc2_kernel(
    const float* __restrict__ bfc2, float* __restrict__ out)
{
    extern __shared__ char smc[];
    bf16*  As  = (bf16*)smc;
    bf16*  Bs  = (bf16*)(smc + 51200);
    float* buf = (float*)(smc + 51200);

    const int tid = threadIdx.x, wid = tid >> 5;
    const int row0 = blockIdx.x * 128;
    const int n0 = blockIdx.y * 96;
    const int mt = wid & 3, ng = wid >> 2;

    FC acc[6];
#pragma unroll
    for (int j = 0; j < 6; j++) wmma::fill_fragment(acc[j], 0.f);

    for (int kc = 0; kc < 4; kc++) {
        __syncthreads();
        stage_A_bf16(As, g_hmid + (size_t)row0 * 768 + kc * 192, 768, tid);
        stage_B96(Bs, g_wfc2 + (size_t)n0 * 768 + kc * 192, 768, tid);
        __syncthreads();
        mma_pass96(As, Bs, mt, ng, acc);
    }

#pragma unroll
    for (int ph = 0; ph < 2; ph++) {
        __syncthreads();
        epi_store48(buf, mt, ng, ph, acc);
        __syncthreads();
        for (int idx = tid; idx < 128 * 48; idx += 256) {
            int r = idx / 48, c = idx - r * 48;
            int gc = n0 + ph * 48 + c;
            size_t gi = (size_t)(row0 + r) * 192 + gc;
            out[gi] = g_xres[gi] + buf[r * 52 + c] + bfc2[gc];
        }
    }
}

// ---------------------------------------------------------------------------

extern "C" void kernel_launch(void* const* d_in, const int* in_sizes, int n_in,
                              void* d_out, int out_size)
{
    const float* x     = (const float*)d_in[0];
    const int*   msk   = (const int*)  d_in[1];
    const float* ln1g  = (const float*)d_in[2];
    const float* ln1b  = (const float*)d_in[3];
    const float* wqkv  = (const float*)d_in[4];
    const float* bqkv  = (const float*)d_in[5];
    const float* wproj = (const float*)d_in[6];
    const float* bproj = (const float*)d_in[7];
    const float* ln2g  = (const float*)d_in[8];
    const float* ln2b  = (const float*)d_in[9];
    const float* wfc1  = (const float*)d_in[10];
    const float* bfc1  = (const float*)d_in[11];
    const float* wfc2  = (const float*)d_in[12];
    const float* bfc2  = (const float*)d_in[13];
    float* out = (float*)d_out;

    cudaFuncSetAttribute(qkv_kernel,  cudaFuncAttributeMaxDynamicSharedMemorySize, GEMM_SM);
    cudaFuncSetAttribute(attn_core,   cudaFuncAttributeMaxDynamicSharedMemorySize, AT_SM);
    cudaFuncSetAttribute(proj_kernel, cudaFuncAttributeMaxDynamicSharedMemorySize, GEMM_SM);
    cudaFuncSetAttribute(fc1_kernel,  cudaFuncAttributeMaxDynamicSharedMemorySize, GEMM_SM);
    cudaFuncSetAttribute(fc2_kernel,  cudaFuncAttributeMaxDynamicSharedMemorySize, GEMM_SM);

    cvt_all<<<576, 256>>>(wqkv, wproj, wfc1, wfc2);
    qkv_kernel<<<1568, 256, GEMM_SM>>>(x, ln1g, ln1b, bqkv);
    attn_core<<<dim3(4096, 6), 256, AT_SM>>>(msk);
    proj_kernel<<<1568, 256, GEMM_SM>>>(x, bproj);
    fc1_kernel<<<1568, 256, GEMM_SM>>>(ln2g, ln2b, bfc1);
    fc2_kernel<<<dim3(1568, 2), 256, GEMM_SM>>>(bfc2, out);
}